// round 2
// baseline (speedup 1.0000x reference)
#include <cuda_runtime.h>
#include <cuda_bf16.h>

// Problem constants (fixed by the reference)
#define BB      2
#define XX      200
#define YY      200
#define ZZ      16      // == HEIGHT, h = 1
#define CC      17
#define CHOOSE  4000
#define EMPTY_LABEL 16

#define TPB 256
#define BLOCKS_PER_Z 16                        // 16*256 = 4096 >= 4000
#define GRID (BB * ZZ * BLOCKS_PER_Z)          // 512

// Persistent device scratch (allocation-free). Counters are MONOTONIC so no
// per-call reset is needed (CUDA-graph replay safe). Partial arrays are
// written before they are read on every call.
__device__ int                 g_cnt_part[GRID];
__device__ float               g_loss_part[GRID];
__device__ unsigned long long  g_bar;     // grid-barrier arrivals (monotonic)
__device__ unsigned long long  g_ticket;  // completion tickets   (monotonic)

__global__ void __launch_bounds__(TPB, 4)
fused_loss(const float* __restrict__ preds,
           const int*   __restrict__ labels,
           const int*   __restrict__ sel,
           float*       __restrict__ out) {
    const int bid = blockIdx.x;
    const int tid = threadIdx.x;
    const int b = bid >> 8;                // bid = b*256 + z*16 + j
    const int z = (bid >> 4) & 15;
    const int j = bid & 15;
    const int m = j * TPB + tid;

    // ---------------- Phase A: per-voxel log(softmax[label] + 1e-3) --------
    bool  valid = false;
    float ll = 0.0f;
    if (m < CHOOSE) {
        const int sbase = (b * CHOOSE + m) * 2;
        const int x = sel[sbase];
        const int y = sel[sbase + 1];
        const int col = (b * XX + x) * YY + y;
        const int lab = labels[col * ZZ + z];
        valid = (lab != EMPTY_LABEL);
        if (valid) {
            const float* __restrict__ p = preds + ((long long)(col * ZZ + z)) * CC;
            float s = 0.0f, vlab = 0.0f;
            #pragma unroll
            for (int c = 0; c < CC; c++) {
                float v = p[c];
                s += __expf(v);                 // preds ~ N(0,1): no overflow
                if (c == lab) vlab = v;         // SEL, no dynamic indexing
            }
            float plab = __fdividef(__expf(vlab), s);
            ll = __logf(plab + 0.001f);
        }
    }

    // per-block valid count -> own slot (plain store, no reset needed)
    int cnt = __syncthreads_count(valid);
    if (tid == 0) {
        g_cnt_part[bid] = cnt;
        __threadfence();
    }

    // ---------------- grid barrier (monotonic epoch counter) ---------------
    __shared__ unsigned long long s_target;
    if (tid == 0) {
        unsigned long long old = atomicAdd(&g_bar, 1ULL);
        s_target = (old / GRID + 1ULL) * GRID;
    }
    __syncthreads();
    if (tid == 0) {
        volatile unsigned long long* vb = (volatile unsigned long long*)&g_bar;
        while (*vb < s_target) { __nanosleep(64); }
        __threadfence();   // acquire: make all g_cnt_part stores visible
    }
    __syncthreads();

    // ---------------- Phase B: weight for this (b,z) -----------------------
    __shared__ int   s_cnt[TPB];
    __shared__ float s_w;
    s_cnt[tid] = g_cnt_part[(b << 8) + tid];   // slot for (b, z=tid>>4, j=tid&15)
    __syncthreads();
    if ((tid & 15) == 0) {                     // 16 threads: per-z sums
        int s = 0;
        #pragma unroll
        for (int k = 0; k < 16; k++) s += s_cnt[tid + k];
        s_cnt[tid] = s;
    }
    __syncthreads();
    if (tid == 0) {
        int maxc = 0;
        #pragma unroll
        for (int z2 = 0; z2 < 16; z2++) maxc = max(maxc, s_cnt[z2 << 4]);
        float maxcf = fmaxf((float)maxc, 1.0f);
        int c = s_cnt[z << 4];
        const float LOG_RATIO = -1.0986122886681098f;   // ln(MIN_W/MAX_W)=ln(1/3)
        s_w = (c > 0) ? 3.0f * __expf(((float)c / maxcf) * LOG_RATIO) : 0.0f;
    }
    __syncthreads();
    const float w = s_w;

    // smooth-L1 of w*ll (0 for invalid: w*0 -> sl=0 matches masked sum)
    float val = 0.0f;
    if (m < CHOOSE && valid) {
        float wl = w * ll;
        float ax = fabsf(wl);
        val = (ax < 1.0f) ? 0.5f * wl * wl : (ax - 0.5f);
    }

    // block reduction (shuffle tree)
    #pragma unroll
    for (int off = 16; off > 0; off >>= 1)
        val += __shfl_down_sync(0xffffffffu, val, off);
    __shared__ float s_warp[TPB / 32];
    const int wid = tid >> 5, lid = tid & 31;
    if (lid == 0) s_warp[wid] = val;
    __syncthreads();
    if (wid == 0) {
        float v = (lid < TPB / 32) ? s_warp[lid] : 0.0f;
        #pragma unroll
        for (int off = 4; off > 0; off >>= 1)
            v += __shfl_down_sync(0xffffffffu, v, off);
        if (lid == 0) {
            g_loss_part[bid] = v;
            __threadfence();
        }
    }

    // ---------------- last-block finalization (ticket) ---------------------
    __shared__ int s_last;
    if (tid == 0) {
        unsigned long long old = atomicAdd(&g_ticket, 1ULL);
        s_last = ((old % GRID) == (GRID - 1)) ? 1 : 0;
    }
    __syncthreads();
    if (!s_last) return;

    __threadfence();  // acquire all partials
    // 512 partials: thread t handles t (batch 0) and 256+t (batch 1)
    float l0 = g_loss_part[tid];
    float l1 = g_loss_part[256 + tid];
    float n0 = (float)g_cnt_part[tid];
    float n1 = (float)g_cnt_part[256 + tid];

    #pragma unroll
    for (int off = 16; off > 0; off >>= 1) {
        l0 += __shfl_down_sync(0xffffffffu, l0, off);
        l1 += __shfl_down_sync(0xffffffffu, l1, off);
        n0 += __shfl_down_sync(0xffffffffu, n0, off);
        n1 += __shfl_down_sync(0xffffffffu, n1, off);
    }
    __shared__ float f0[8], f1[8], c0[8], c1[8];
    if (lid == 0) { f0[wid] = l0; f1[wid] = l1; c0[wid] = n0; c1[wid] = n1; }
    __syncthreads();
    if (wid == 0) {
        float a0 = (lid < 8) ? f0[lid] : 0.0f;
        float a1 = (lid < 8) ? f1[lid] : 0.0f;
        float b0 = (lid < 8) ? c0[lid] : 0.0f;
        float b1 = (lid < 8) ? c1[lid] : 0.0f;
        #pragma unroll
        for (int off = 4; off > 0; off >>= 1) {
            a0 += __shfl_down_sync(0xffffffffu, a0, off);
            a1 += __shfl_down_sync(0xffffffffu, a1, off);
            b0 += __shfl_down_sync(0xffffffffu, b0, off);
            b1 += __shfl_down_sync(0xffffffffu, b1, off);
        }
        if (lid == 0) {
            float r0 = a0 / fmaxf(b0, 1.0f);
            float r1 = a1 / fmaxf(b1, 1.0f);
            out[0] = 0.5f * (r0 + r1);
        }
    }
}

extern "C" void kernel_launch(void* const* d_in, const int* in_sizes, int n_in,
                              void* d_out, int out_size) {
    const float* preds  = nullptr;
    const int*   labels = nullptr;
    const int*   sel    = nullptr;
    for (int i = 0; i < n_in; i++) {
        if (in_sizes[i] == BB * XX * YY * ZZ * CC)      preds  = (const float*)d_in[i];
        else if (in_sizes[i] == BB * XX * YY * ZZ)      labels = (const int*)d_in[i];
        else if (in_sizes[i] == BB * CHOOSE * 2)        sel    = (const int*)d_in[i];
    }
    fused_loss<<<GRID, TPB>>>(preds, labels, sel, (float*)d_out);
}

// round 3
// speedup vs baseline: 1.0134x; 1.0134x over previous
#include <cuda_runtime.h>
#include <cuda_bf16.h>

// Problem constants (fixed by the reference)
#define BB      2
#define XX      200
#define YY      200
#define ZZ      16      // == HEIGHT, h = 1
#define CC      17
#define EMPTY_LABEL 16
#define CHOOSE  4000

#define TPB 256
#define BLOCKS_PER_Z 16                        // 16*256 = 4096 >= 4000
#define GRID (BB * ZZ * BLOCKS_PER_Z)          // 512

#define NPOLY 6                                // classes 0..5 via FMA-pipe poly exp

// Persistent device scratch (allocation-free). Counters are MONOTONIC so no
// per-call reset is needed (CUDA-graph replay safe).
__device__ int                 g_cnt_part[GRID];
__device__ float               g_loss_part[GRID];
__device__ unsigned long long  g_bar;     // grid-barrier arrivals (monotonic)
__device__ unsigned long long  g_ticket;  // completion tickets   (monotonic)

// ---- f32x2 packed-math helpers (Blackwell) ---------------------------------
__device__ __forceinline__ unsigned long long f2pk(float a, float b) {
    unsigned long long r;
    asm("mov.b64 %0,{%1,%2};" : "=l"(r) : "f"(a), "f"(b));
    return r;
}
__device__ __forceinline__ unsigned long long f2pku(unsigned a, unsigned b) {
    unsigned long long r;
    asm("mov.b64 %0,{%1,%2};" : "=l"(r) : "r"(a), "r"(b));
    return r;
}
__device__ __forceinline__ void f2up(unsigned long long v, unsigned& a, unsigned& b) {
    asm("mov.b64 {%0,%1},%2;" : "=r"(a), "=r"(b) : "l"(v));
}
__device__ __forceinline__ void f2upf(unsigned long long v, float& a, float& b) {
    asm("mov.b64 {%0,%1},%2;" : "=f"(a), "=f"(b) : "l"(v));
}
__device__ __forceinline__ unsigned long long f2mul(unsigned long long a, unsigned long long b) {
    unsigned long long r;
    asm("mul.rn.f32x2 %0,%1,%2;" : "=l"(r) : "l"(a), "l"(b));
    return r;
}
__device__ __forceinline__ unsigned long long f2add(unsigned long long a, unsigned long long b) {
    unsigned long long r;
    asm("add.rn.f32x2 %0,%1,%2;" : "=l"(r) : "l"(a), "l"(b));
    return r;
}
__device__ __forceinline__ unsigned long long f2fma(unsigned long long a, unsigned long long b,
                                                    unsigned long long c) {
    unsigned long long r;
    asm("fma.rn.f32x2 %0,%1,%2,%3;" : "=l"(r) : "l"(a), "l"(b), "l"(c));
    return r;
}
__device__ __forceinline__ float ex2f(float x) {
    float y; asm("ex2.approx.f32 %0,%1;" : "=f"(y) : "f"(x)); return y;
}

__global__ void __launch_bounds__(TPB, 4)
fused_loss(const float* __restrict__ preds,
           const int*   __restrict__ labels,
           const int*   __restrict__ sel,
           float*       __restrict__ out) {
    const int bid = blockIdx.x;
    const int tid = threadIdx.x;
    const int b = bid >> 8;                // bid = b*256 + z*16 + j
    const int z = (bid >> 4) & 15;
    const int j = bid & 15;
    const int m = j * TPB + tid;

    // Packed constants (hoisted/CSE'd by compiler; ALU pipe is idle anyway)
    const float L2E = 1.4426950408889634f;
    const unsigned long long L2E2 = f2pk(L2E, L2E);
    const unsigned long long MG2  = f2pk(12582912.0f, 12582912.0f);   // 1.5*2^23
    const unsigned long long NMG2 = f2pk(-12582912.0f, -12582912.0f);
    const unsigned long long N12  = f2pk(-1.0f, -1.0f);
    const unsigned long long A42  = f2pk(9.61812910e-3f, 9.61812910e-3f); // ln^4(2)/24
    const unsigned long long A32  = f2pk(5.55041087e-2f, 5.55041087e-2f); // ln^3(2)/6
    const unsigned long long A22  = f2pk(2.40226507e-1f, 2.40226507e-1f); // ln^2(2)/2
    const unsigned long long A12  = f2pk(6.93147181e-1f, 6.93147181e-1f); // ln(2)
    const unsigned long long ONE2 = f2pk(1.0f, 1.0f);

    // ---------------- Phase A: per-voxel log(softmax[label] + 1e-3) --------
    bool  valid = false;
    float ll = 0.0f;
    if (m < CHOOSE) {
        const int2 xy = ((const int2*)sel)[b * CHOOSE + m];   // 8B-aligned
        const int col = (b * XX + xy.x) * YY + xy.y;
        const int lab = labels[col * ZZ + z];
        valid = (lab != EMPTY_LABEL);
        if (valid) {
            const float* __restrict__ p = preds + (long long)(col * ZZ + z) * CC;
            float v[CC];
            #pragma unroll
            for (int c = 0; c < CC; c++) v[c] = __ldg(p + c);
            const float vlab = __ldg(p + lab);                // L1 hit

            // FMA-pipe poly exp for classes 0..NPOLY-1 (packed pairs)
            unsigned long long acc2 = f2pk(0.0f, 0.0f);
            #pragma unroll
            for (int i = 0; i < NPOLY / 2; i++) {
                unsigned long long v2 = f2pk(v[2 * i], v[2 * i + 1]);
                unsigned long long y2 = f2mul(v2, L2E2);
                unsigned long long r2 = f2add(y2, MG2);        // round-to-int trick
                unsigned long long t2 = f2add(r2, NMG2);       // t = rni(y)
                unsigned long long f2 = f2fma(t2, N12, y2);    // f = y - t, |f|<=0.5
                unsigned long long pp = f2fma(f2, A42, A32);   // Horner for 2^f
                pp = f2fma(pp, f2, A22);
                pp = f2fma(pp, f2, A12);
                pp = f2fma(pp, f2, ONE2);
                unsigned rl, rh;
                f2up(r2, rl, rh);                              // int part in low bits
                unsigned sl = (rl << 23) + 0x3F800000u;        // bits of 2^i
                unsigned sh = (rh << 23) + 0x3F800000u;
                acc2 = f2fma(pp, f2pku(sl, sh), acc2);         // acc += 2^f * 2^i
            }

            // MUFU ex2 for classes NPOLY..16
            float s1 = 0.0f;
            #pragma unroll
            for (int c = NPOLY; c < CC; c++) s1 += ex2f(v[c] * L2E);

            float alo, ahi;
            f2upf(acc2, alo, ahi);
            const float S = s1 + alo + ahi;

            const float elab = ex2f(vlab * L2E);
            const float plab = __fdividef(elab, S);
            ll = __logf(plab + 0.001f);
        }
    }

    // per-block valid count -> own slot (plain store, no reset needed)
    int cnt = __syncthreads_count(valid);
    if (tid == 0) {
        g_cnt_part[bid] = cnt;
        __threadfence();
    }

    // ---------------- grid barrier (monotonic epoch counter) ---------------
    __shared__ unsigned long long s_target;
    if (tid == 0) {
        unsigned long long old = atomicAdd(&g_bar, 1ULL);
        s_target = (old / GRID + 1ULL) * GRID;
    }
    __syncthreads();
    if (tid == 0) {
        volatile unsigned long long* vb = (volatile unsigned long long*)&g_bar;
        while (*vb < s_target) { __nanosleep(64); }
        __threadfence();   // acquire: make all g_cnt_part stores visible
    }
    __syncthreads();

    // ---------------- Phase B: weight for this (b,z) -----------------------
    __shared__ int   s_cnt[TPB];
    __shared__ float s_w;
    s_cnt[tid] = g_cnt_part[(b << 8) + tid];   // slot for (b, z=tid>>4, j=tid&15)
    __syncthreads();
    if ((tid & 15) == 0) {                     // 16 threads: per-z sums
        int s = 0;
        #pragma unroll
        for (int k = 0; k < 16; k++) s += s_cnt[tid + k];
        s_cnt[tid] = s;
    }
    __syncthreads();
    if (tid == 0) {
        int maxc = 0;
        #pragma unroll
        for (int z2 = 0; z2 < 16; z2++) maxc = max(maxc, s_cnt[z2 << 4]);
        float maxcf = fmaxf((float)maxc, 1.0f);
        int c = s_cnt[z << 4];
        const float LOG_RATIO = -1.0986122886681098f;   // ln(MIN_W/MAX_W)=ln(1/3)
        s_w = (c > 0) ? 3.0f * __expf(((float)c / maxcf) * LOG_RATIO) : 0.0f;
    }
    __syncthreads();
    const float w = s_w;

    // smooth-L1 of w*ll (0 for invalid: matches masked sum exactly)
    float val = 0.0f;
    if (valid) {
        float wl = w * ll;
        float ax = fabsf(wl);
        val = (ax < 1.0f) ? 0.5f * wl * wl : (ax - 0.5f);
    }

    // block reduction (shuffle tree)
    #pragma unroll
    for (int off = 16; off > 0; off >>= 1)
        val += __shfl_down_sync(0xffffffffu, val, off);
    __shared__ float s_warp[TPB / 32];
    const int wid = tid >> 5, lid = tid & 31;
    if (lid == 0) s_warp[wid] = val;
    __syncthreads();
    if (wid == 0) {
        float v = (lid < TPB / 32) ? s_warp[lid] : 0.0f;
        #pragma unroll
        for (int off = 4; off > 0; off >>= 1)
            v += __shfl_down_sync(0xffffffffu, v, off);
        if (lid == 0) {
            g_loss_part[bid] = v;
            __threadfence();
        }
    }

    // ---------------- last-block finalization (ticket) ---------------------
    __shared__ int s_last;
    if (tid == 0) {
        unsigned long long old = atomicAdd(&g_ticket, 1ULL);
        s_last = ((old % GRID) == (GRID - 1)) ? 1 : 0;
    }
    __syncthreads();
    if (!s_last) return;

    __threadfence();  // acquire all partials
    float l0 = g_loss_part[tid];
    float l1 = g_loss_part[256 + tid];
    float n0 = (float)g_cnt_part[tid];
    float n1 = (float)g_cnt_part[256 + tid];

    #pragma unroll
    for (int off = 16; off > 0; off >>= 1) {
        l0 += __shfl_down_sync(0xffffffffu, l0, off);
        l1 += __shfl_down_sync(0xffffffffu, l1, off);
        n0 += __shfl_down_sync(0xffffffffu, n0, off);
        n1 += __shfl_down_sync(0xffffffffu, n1, off);
    }
    __shared__ float f0[8], f1[8], c0[8], c1[8];
    if (lid == 0) { f0[wid] = l0; f1[wid] = l1; c0[wid] = n0; c1[wid] = n1; }
    __syncthreads();
    if (wid == 0) {
        float a0 = (lid < 8) ? f0[lid] : 0.0f;
        float a1 = (lid < 8) ? f1[lid] : 0.0f;
        float b0 = (lid < 8) ? c0[lid] : 0.0f;
        float b1 = (lid < 8) ? c1[lid] : 0.0f;
        #pragma unroll
        for (int off = 4; off > 0; off >>= 1) {
            a0 += __shfl_down_sync(0xffffffffu, a0, off);
            a1 += __shfl_down_sync(0xffffffffu, a1, off);
            b0 += __shfl_down_sync(0xffffffffu, b0, off);
            b1 += __shfl_down_sync(0xffffffffu, b1, off);
        }
        if (lid == 0) {
            float r0 = a0 / fmaxf(b0, 1.0f);
            float r1 = a1 / fmaxf(b1, 1.0f);
            out[0] = 0.5f * (r0 + r1);
        }
    }
}

extern "C" void kernel_launch(void* const* d_in, const int* in_sizes, int n_in,
                              void* d_out, int out_size) {
    const float* preds  = nullptr;
    const int*   labels = nullptr;
    const int*   sel    = nullptr;
    for (int i = 0; i < n_in; i++) {
        if (in_sizes[i] == BB * XX * YY * ZZ * CC)      preds  = (const float*)d_in[i];
        else if (in_sizes[i] == BB * XX * YY * ZZ)      labels = (const int*)d_in[i];
        else if (in_sizes[i] == BB * CHOOSE * 2)        sel    = (const int*)d_in[i];
    }
    fused_loss<<<GRID, TPB>>>(preds, labels, sel, (float*)d_out);
}

// round 4
// speedup vs baseline: 1.3714x; 1.3532x over previous
#include <cuda_runtime.h>
#include <cuda_bf16.h>

// Problem constants (fixed by the reference)
#define BB      2
#define XX      200
#define YY      200
#define ZZ      16      // == HEIGHT, h = 1
#define CC      17
#define EMPTY_LABEL 16
#define CHOOSE  4000

#define TPB 256
#define COLS_PER_BLK 16                       // 16 cols x 16 z = 256 voxels/block
#define BLKS_PER_B (CHOOSE / COLS_PER_BLK)    // 250
#define GRID (BB * BLKS_PER_B)                // 500

// Persistent device scratch (allocation-free).
// g_cnt / g_loss are zero-initialized at load and re-zeroed by the last block
// of every call (after use), so every call starts from zeros (replay-safe).
// g_bar / g_ticket are MONOTONIC epoch counters (never reset).
__device__ int                 g_cnt[BB * ZZ];     // valid count per (b,z)
__device__ float               g_loss[BB];         // per-batch loss sum
__device__ unsigned long long  g_bar;
__device__ unsigned long long  g_ticket;

__global__ void __launch_bounds__(TPB, 4)
fused_loss(const float* __restrict__ preds,
           const int*   __restrict__ labels,
           const int*   __restrict__ sel,
           float*       __restrict__ out) {
    const int bid = blockIdx.x;
    const int tid = threadIdx.x;
    const int b  = bid / BLKS_PER_B;
    const int cb = bid % BLKS_PER_B;          // column-group within batch

    __shared__ float s_pred[COLS_PER_BLK * ZZ * CC];   // 16*272 floats = 17408B
    __shared__ int   s_lab [COLS_PER_BLK * ZZ];        // 1KB
    __shared__ int   s_col [COLS_PER_BLK];
    __shared__ int   s_zcnt[ZZ];
    __shared__ float s_w   [ZZ];

    // ---- stage sel -> column indices; zero per-z counters -----------------
    if (tid < COLS_PER_BLK) {
        int2 xy = ((const int2*)sel)[b * CHOOSE + cb * COLS_PER_BLK + tid];
        s_col[tid] = (b * XX + xy.x) * YY + xy.y;
    } else if (tid < 2 * COLS_PER_BLK) {
        s_zcnt[tid - COLS_PER_BLK] = 0;
    }
    __syncthreads();

    // ---- stage labels (16 cols x 16 z, int4 coalesced) ---------------------
    if (tid < 64) {
        int lc = tid >> 2, i4 = tid & 3;
        ((int4*)s_lab)[lc * 4 + i4] =
            ((const int4*)(labels + (long long)s_col[lc] * ZZ))[i4];
    }

    // ---- stage preds (16 cols x 1088B, float4 coalesced) -------------------
    {
        const int w = tid >> 5, lane = tid & 31;
        #pragma unroll
        for (int cc = 0; cc < 2; cc++) {
            const int lc = w * 2 + cc;
            const float4* __restrict__ src =
                (const float4*)preds + (long long)s_col[lc] * 68;  // 272 floats
            float4* dst = (float4*)(s_pred + lc * (ZZ * CC));
            dst[lane]      = src[lane];
            dst[lane + 32] = src[lane + 32];
            if (lane < 4) dst[lane + 64] = src[lane + 64];
        }
    }
    __syncthreads();

    // ---- per-voxel log(softmax[label] + 1e-3) from smem --------------------
    const int lc = tid >> 4;          // local column 0..15
    const int z  = tid & 15;
    const int lab = s_lab[lc * ZZ + z];
    const bool valid = (lab != EMPTY_LABEL);
    float ll = 0.0f;
    if (valid) {
        const float* __restrict__ p = s_pred + lc * (ZZ * CC) + z * CC;
        float s = 0.0f;
        #pragma unroll
        for (int c = 0; c < CC; c++) s += __expf(p[c]);   // conflict-free LDS
        const float plab = __fdividef(__expf(p[lab]), s);
        ll = __logf(plab + 0.001f);
        atomicAdd(&s_zcnt[z], 1);
    }
    __syncthreads();

    // ---- publish per-(b,z) counts ------------------------------------------
    if (tid < ZZ) {
        if (s_zcnt[tid]) atomicAdd(&g_cnt[b * ZZ + tid], s_zcnt[tid]);
    }
    __threadfence();

    // ---- grid barrier (monotonic epoch counter) ----------------------------
    __shared__ unsigned long long s_target;
    if (tid == 0) {
        unsigned long long old = atomicAdd(&g_bar, 1ULL);
        s_target = (old / GRID + 1ULL) * GRID;
    }
    __syncthreads();
    if (tid == 0) {
        volatile unsigned long long* vb = (volatile unsigned long long*)&g_bar;
        while (*vb < s_target) { __nanosleep(32); }
        __threadfence();   // acquire: all g_cnt updates visible
    }
    __syncthreads();

    // ---- weights for this batch --------------------------------------------
    __shared__ int s_ci[ZZ];
    if (tid < ZZ) s_ci[tid] = g_cnt[b * ZZ + tid];
    __syncthreads();
    if (tid < ZZ) {
        int maxc = 0;
        #pragma unroll
        for (int z2 = 0; z2 < ZZ; z2++) maxc = max(maxc, s_ci[z2]);
        float maxcf = fmaxf((float)maxc, 1.0f);
        int c = s_ci[tid];
        const float LOG_RATIO = -1.0986122886681098f;   // ln(1/3)
        s_w[tid] = (c > 0) ? 3.0f * __expf(((float)c / maxcf) * LOG_RATIO) : 0.0f;
    }
    __syncthreads();

    // ---- smooth-L1 + block reduce -> per-batch atomic -----------------------
    float val = 0.0f;
    if (valid) {
        float wl = s_w[z] * ll;
        float ax = fabsf(wl);
        val = (ax < 1.0f) ? 0.5f * wl * wl : (ax - 0.5f);
    }
    #pragma unroll
    for (int off = 16; off > 0; off >>= 1)
        val += __shfl_down_sync(0xffffffffu, val, off);
    __shared__ float s_warp[TPB / 32];
    const int wid = tid >> 5, lid = tid & 31;
    if (lid == 0) s_warp[wid] = val;
    __syncthreads();
    if (wid == 0) {
        float v = (lid < TPB / 32) ? s_warp[lid] : 0.0f;
        #pragma unroll
        for (int off = 4; off > 0; off >>= 1)
            v += __shfl_down_sync(0xffffffffu, v, off);
        if (lid == 0) {
            atomicAdd(&g_loss[b], v);
            __threadfence();
        }
    }
    __syncthreads();

    // ---- last block: finalize + reset accumulators for next replay ----------
    __shared__ int s_last;
    if (tid == 0) {
        unsigned long long old = atomicAdd(&g_ticket, 1ULL);
        s_last = ((old % GRID) == (GRID - 1)) ? 1 : 0;
    }
    __syncthreads();
    if (!s_last) return;

    if (tid == 0) {
        __threadfence();  // acquire all g_loss / g_cnt updates
        int n0 = 0, n1 = 0;
        #pragma unroll
        for (int z2 = 0; z2 < ZZ; z2++) { n0 += g_cnt[z2]; n1 += g_cnt[ZZ + z2]; }
        float r0 = g_loss[0] / fmaxf((float)n0, 1.0f);
        float r1 = g_loss[1] / fmaxf((float)n1, 1.0f);
        out[0] = 0.5f * (r0 + r1);
        // reset for next call (graph replay / re-validation)
        #pragma unroll
        for (int z2 = 0; z2 < BB * ZZ; z2++) g_cnt[z2] = 0;
        g_loss[0] = 0.0f;
        g_loss[1] = 0.0f;
    }
}

extern "C" void kernel_launch(void* const* d_in, const int* in_sizes, int n_in,
                              void* d_out, int out_size) {
    const float* preds  = nullptr;
    const int*   labels = nullptr;
    const int*   sel    = nullptr;
    for (int i = 0; i < n_in; i++) {
        if (in_sizes[i] == BB * XX * YY * ZZ * CC)      preds  = (const float*)d_in[i];
        else if (in_sizes[i] == BB * XX * YY * ZZ)      labels = (const int*)d_in[i];
        else if (in_sizes[i] == BB * CHOOSE * 2)        sel    = (const int*)d_in[i];
    }
    fused_loss<<<GRID, TPB>>>(preds, labels, sel, (float*)d_out);
}